// round 2
// baseline (speedup 1.0000x reference)
#include <cuda_runtime.h>
#include <cuda_bf16.h>

#define N_NODES 50000
#define IN_CH 64
#define HID 128

// Scratch (device globals -- no allocation allowed)
__device__ float g_cnt[N_NODES];
__device__ float g_agg[N_NODES * HID];
__device__ float g_h1[N_NODES * HID];
__device__ float g_h2[N_NODES * HID];

// ---------------------------------------------------------------------------
// Zero kernels
// ---------------------------------------------------------------------------
__global__ void zero_cnt_agg64(int n) {
    int i = blockIdx.x * blockDim.x + threadIdx.x;
    if (i < n * IN_CH) g_agg[i] = 0.0f;
    if (i < n)         g_cnt[i] = 0.0f;
}

__global__ void zero_agg128(int n) {
    int i = blockIdx.x * blockDim.x + threadIdx.x;
    if (i < n * HID) g_agg[i] = 0.0f;
}

// ---------------------------------------------------------------------------
// Scatter: one warp per edge. Layer0: 64 feats (float2/lane). Also counts.
// edge_index is int32 (JAX demotes int64 without x64 mode).
// ---------------------------------------------------------------------------
__global__ void scatter64(const int* __restrict__ ei,
                          const float* __restrict__ ew,
                          const float* __restrict__ h, int E) {
    int gid  = blockIdx.x * blockDim.x + threadIdx.x;
    int e    = gid >> 5;
    if (e >= E) return;
    int lane = gid & 31;

    int src = ei[e];
    int dst = ei[E + e];
    float w = ew[e];

    float2 v = reinterpret_cast<const float2*>(h + (long long)src * IN_CH)[lane];
    v.x *= w; v.y *= w;
    atomicAdd(reinterpret_cast<float2*>(&g_agg[(long long)dst * IN_CH]) + lane, v);
    if (lane == 0) atomicAdd(&g_cnt[dst], 1.0f);
}

// Layer1: 128 feats (float4/lane)
__global__ void scatter128(const int* __restrict__ ei,
                           const float* __restrict__ ew,
                           const float* __restrict__ h, int E) {
    int gid  = blockIdx.x * blockDim.x + threadIdx.x;
    int e    = gid >> 5;
    if (e >= E) return;
    int lane = gid & 31;

    int src = ei[e];
    int dst = ei[E + e];
    float w = ew[e];

    float4 v = reinterpret_cast<const float4*>(h + (long long)src * HID)[lane];
    v.x *= w; v.y *= w; v.z *= w; v.w *= w;
    atomicAdd(reinterpret_cast<float4*>(&g_agg[(long long)dst * HID]) + lane, v);
}

// ---------------------------------------------------------------------------
// Graph conv: h_out = relu( (agg/denom) @ W_rel^T + b_rel + h_in @ W_root^T )
// One block per node, 128 threads, one output channel per thread.
// ---------------------------------------------------------------------------
template <int K>
__global__ void conv_kernel(const float* __restrict__ hin,
                            const float* __restrict__ Wrel,
                            const float* __restrict__ brel,
                            const float* __restrict__ Wroot,
                            float* __restrict__ hout) {
    int n = blockIdx.x;
    int o = threadIdx.x;  // 0..127

    __shared__ float s_in[K];
    __shared__ float s_agg[K];

    float inv = 1.0f / fmaxf(g_cnt[n], 1.0f);
    for (int k = o; k < K; k += HID) {
        s_in[k]  = hin[(long long)n * K + k];
        s_agg[k] = g_agg[(long long)n * K + k] * inv;
    }
    __syncthreads();

    const float4* wr = reinterpret_cast<const float4*>(Wrel  + o * K);
    const float4* wo = reinterpret_cast<const float4*>(Wroot + o * K);
    const float4* sa = reinterpret_cast<const float4*>(s_agg);
    const float4* si = reinterpret_cast<const float4*>(s_in);

    float acc1 = brel[o];
    float acc2 = 0.0f;
#pragma unroll 8
    for (int k = 0; k < K / 4; k++) {
        float4 a = sa[k], b = wr[k];
        float4 c = si[k], d = wo[k];
        acc1 += a.x * b.x + a.y * b.y + a.z * b.z + a.w * b.w;
        acc2 += c.x * d.x + c.y * d.y + c.z * d.z + c.w * d.w;
    }
    hout[(long long)n * HID + o] = fmaxf(acc1 + acc2, 0.0f);
}

// ---------------------------------------------------------------------------
// Readout: h_out = relu( h_in @ W^T + b ), K = 128
// ---------------------------------------------------------------------------
__global__ void ro_kernel(const float* __restrict__ hin,
                          const float* __restrict__ W,
                          const float* __restrict__ b,
                          float* __restrict__ hout) {
    int n = blockIdx.x;
    int o = threadIdx.x;

    __shared__ float s_in[HID];
    s_in[o] = hin[(long long)n * HID + o];
    __syncthreads();

    const float4* wp = reinterpret_cast<const float4*>(W + o * HID);
    const float4* si = reinterpret_cast<const float4*>(s_in);

    float acc = b[o];
#pragma unroll 8
    for (int k = 0; k < HID / 4; k++) {
        float4 c = si[k], d = wp[k];
        acc += c.x * d.x + c.y * d.y + c.z * d.z + c.w * d.w;
    }
    hout[(long long)n * HID + o] = fmaxf(acc, 0.0f);
}

// ---------------------------------------------------------------------------
// Final: h4 = relu(h_in @ W_ro1^T + b_ro1); out = h4 @ W_prd^T + b_prd
// ---------------------------------------------------------------------------
__global__ void final_kernel(const float* __restrict__ hin,
                             const float* __restrict__ W,
                             const float* __restrict__ b,
                             const float* __restrict__ Wprd,
                             const float* __restrict__ bprd,
                             float* __restrict__ out) {
    int n = blockIdx.x;
    int o = threadIdx.x;

    __shared__ float s_in[HID];
    __shared__ float s_part[4];
    s_in[o] = hin[(long long)n * HID + o];
    __syncthreads();

    const float4* wp = reinterpret_cast<const float4*>(W + o * HID);
    const float4* si = reinterpret_cast<const float4*>(s_in);

    float acc = b[o];
#pragma unroll 8
    for (int k = 0; k < HID / 4; k++) {
        float4 c = si[k], d = wp[k];
        acc += c.x * d.x + c.y * d.y + c.z * d.z + c.w * d.w;
    }
    float v = fmaxf(acc, 0.0f) * Wprd[o];

    // warp reduce
#pragma unroll
    for (int off = 16; off > 0; off >>= 1)
        v += __shfl_down_sync(0xFFFFFFFFu, v, off);
    if ((o & 31) == 0) s_part[o >> 5] = v;
    __syncthreads();
    if (o == 0)
        out[n] = s_part[0] + s_part[1] + s_part[2] + s_part[3] + bprd[0];
}

// ---------------------------------------------------------------------------
extern "C" void kernel_launch(void* const* d_in, const int* in_sizes, int n_in,
                              void* d_out, int out_size) {
    const float* x     = (const float*)d_in[0];   // (N,1,64)
    const int*   ei    = (const int*)d_in[1];     // (2,E) int32 (JAX demoted)
    const float* ew    = (const float*)d_in[2];   // (E,)
    const float* Wrel0 = (const float*)d_in[3];
    const float* brel0 = (const float*)d_in[4];
    const float* Wroot0= (const float*)d_in[5];
    const float* Wro0  = (const float*)d_in[6];
    const float* bro0  = (const float*)d_in[7];
    const float* Wrel1 = (const float*)d_in[8];
    const float* brel1 = (const float*)d_in[9];
    const float* Wroot1= (const float*)d_in[10];
    const float* Wro1  = (const float*)d_in[11];
    const float* bro1  = (const float*)d_in[12];
    const float* Wprd  = (const float*)d_in[13];
    const float* bprd  = (const float*)d_in[14];
    float*       out   = (float*)d_out;

    int N = in_sizes[0] / IN_CH;  // 50000
    int E = in_sizes[2];          // 800000

    float* h1; cudaGetSymbolAddress((void**)&h1, g_h1);
    float* h2; cudaGetSymbolAddress((void**)&h2, g_h2);

    int zthreads = 256;

    // --- layer 0 ---
    zero_cnt_agg64<<<(N * IN_CH + zthreads - 1) / zthreads, zthreads>>>(N);
    {
        long long total = (long long)E * 32;
        int blocks = (int)((total + 255) / 256);
        scatter64<<<blocks, 256>>>(ei, ew, x, E);
    }
    conv_kernel<IN_CH><<<N, HID>>>(x, Wrel0, brel0, Wroot0, h1);
    ro_kernel<<<N, HID>>>(h1, Wro0, bro0, h2);

    // --- layer 1 ---
    zero_agg128<<<(N * HID + zthreads - 1) / zthreads, zthreads>>>(N);
    {
        long long total = (long long)E * 32;
        int blocks = (int)((total + 255) / 256);
        scatter128<<<blocks, 256>>>(ei, ew, h2, E);
    }
    conv_kernel<HID><<<N, HID>>>(h2, Wrel1, brel1, Wroot1, h1);

    // --- readout + head ---
    final_kernel<<<N, HID>>>(h1, Wro1, bro1, Wprd, bprd, out);
}

// round 3
// speedup vs baseline: 7.3302x; 7.3302x over previous
#include <cuda_runtime.h>
#include <cuda_bf16.h>

#define N_NODES 50000
#define IN_CH 64
#define HID 128

// Scratch (device globals -- no allocation allowed)
__device__ float g_cnt[N_NODES];
__device__ float g_agg[N_NODES * HID];
__device__ float g_h1[N_NODES * HID];
__device__ float g_h2[N_NODES * HID];

// ---------------------------------------------------------------------------
// Zero kernels
// ---------------------------------------------------------------------------
__global__ void zero_cnt_agg64(int n) {
    int i = blockIdx.x * blockDim.x + threadIdx.x;
    if (i < n * IN_CH) g_agg[i] = 0.0f;
    if (i < n)         g_cnt[i] = 0.0f;
}

__global__ void zero_agg128(int n) {
    int i = blockIdx.x * blockDim.x + threadIdx.x;
    if (i < n * HID) g_agg[i] = 0.0f;
}

// invert counts in place: g_cnt[i] = 1 / max(cnt, 1)
__global__ void inv_cnt(int n) {
    int i = blockIdx.x * blockDim.x + threadIdx.x;
    if (i < n) g_cnt[i] = 1.0f / fmaxf(g_cnt[i], 1.0f);
}

// scale agg rows by inverted count
template <int K>
__global__ void scale_agg(int n) {
    int i = blockIdx.x * blockDim.x + threadIdx.x;
    if (i < n * K) g_agg[i] *= g_cnt[i / K];
}

// ---------------------------------------------------------------------------
// Scatter: one warp per edge. Layer0: 64 feats (float2/lane). Also counts.
// ---------------------------------------------------------------------------
__global__ void scatter64(const int* __restrict__ ei,
                          const float* __restrict__ ew,
                          const float* __restrict__ h, int E) {
    int gid  = blockIdx.x * blockDim.x + threadIdx.x;
    int e    = gid >> 5;
    if (e >= E) return;
    int lane = gid & 31;

    int src = ei[e];
    int dst = ei[E + e];
    float w = ew[e];

    float2 v = reinterpret_cast<const float2*>(h + (long long)src * IN_CH)[lane];
    v.x *= w; v.y *= w;
    atomicAdd(reinterpret_cast<float2*>(&g_agg[(long long)dst * IN_CH]) + lane, v);
    if (lane == 0) atomicAdd(&g_cnt[dst], 1.0f);
}

__global__ void scatter128(const int* __restrict__ ei,
                           const float* __restrict__ ew,
                           const float* __restrict__ h, int E) {
    int gid  = blockIdx.x * blockDim.x + threadIdx.x;
    int e    = gid >> 5;
    if (e >= E) return;
    int lane = gid & 31;

    int src = ei[e];
    int dst = ei[E + e];
    float w = ew[e];

    float4 v = reinterpret_cast<const float4*>(h + (long long)src * HID)[lane];
    v.x *= w; v.y *= w; v.z *= w; v.w *= w;
    atomicAdd(reinterpret_cast<float4*>(&g_agg[(long long)dst * HID]) + lane, v);
}

// ---------------------------------------------------------------------------
// Tiled SGEMM: Y[M x 128] = act( A1 @ B1^T (+ A2 @ B2^T) + bias )
//   A: [M x K] row-major (node features), B: [128 x K] row-major (out x in)
//   BM=BN=128, BK=32, 256 threads, each computes an 8x8 micro-tile.
//   HEAD: fuse out[m] = sum_n relu(y[m,n]) * Wprd[n] + bprd
// ---------------------------------------------------------------------------
#define BM 128
#define BN 128
#define BK 32

template <int K, bool DUAL, bool HEAD>
__global__ __launch_bounds__(256, 2)
void gemm_kernel(const float* __restrict__ A1,
                 const float* __restrict__ B1,
                 const float* __restrict__ A2,
                 const float* __restrict__ B2,
                 const float* __restrict__ bias,
                 const float* __restrict__ Wprd,
                 const float* __restrict__ bprd,
                 float* __restrict__ Y, int M) {
    __shared__ float As[BK][BM];
    __shared__ float Bs[BK][BN];

    int tid = threadIdx.x;
    int tn  = tid & 15;   // 0..15 -> output cols tn*8..tn*8+7
    int tm  = tid >> 4;   // 0..15 -> rows tm*8..tm*8+7
    int m0  = blockIdx.x * BM;

    float acc[8][8];
#pragma unroll
    for (int i = 0; i < 8; i++)
#pragma unroll
        for (int j = 0; j < 8; j++) acc[i][j] = 0.0f;

    const int NSRC = DUAL ? 2 : 1;
    for (int s = 0; s < NSRC; s++) {
        const float* A = (DUAL && s) ? A2 : A1;
        const float* B = (DUAL && s) ? B2 : B1;

        for (int k0 = 0; k0 < K; k0 += BK) {
            // cooperative load: f = tid + 256*q; m = f&127; k4 = f>>7 (0..7)
#pragma unroll
            for (int q = 0; q < 4; q++) {
                int f  = tid + 256 * q;
                int m  = f & 127;
                int k4 = f >> 7;
                int row = m0 + m;
                float4 v = make_float4(0.f, 0.f, 0.f, 0.f);
                if (row < M)
                    v = *reinterpret_cast<const float4*>(A + (long long)row * K + k0 + k4 * 4);
                As[k4 * 4 + 0][m] = v.x;
                As[k4 * 4 + 1][m] = v.y;
                As[k4 * 4 + 2][m] = v.z;
                As[k4 * 4 + 3][m] = v.w;
                float4 w = *reinterpret_cast<const float4*>(B + (long long)m * K + k0 + k4 * 4);
                Bs[k4 * 4 + 0][m] = w.x;
                Bs[k4 * 4 + 1][m] = w.y;
                Bs[k4 * 4 + 2][m] = w.z;
                Bs[k4 * 4 + 3][m] = w.w;
            }
            __syncthreads();

#pragma unroll
            for (int kk = 0; kk < BK; kk++) {
                float4 a0 = *reinterpret_cast<const float4*>(&As[kk][tm * 8]);
                float4 a1 = *reinterpret_cast<const float4*>(&As[kk][tm * 8 + 4]);
                float4 b0 = *reinterpret_cast<const float4*>(&Bs[kk][tn * 8]);
                float4 b1 = *reinterpret_cast<const float4*>(&Bs[kk][tn * 8 + 4]);
                float a[8] = {a0.x, a0.y, a0.z, a0.w, a1.x, a1.y, a1.z, a1.w};
                float b[8] = {b0.x, b0.y, b0.z, b0.w, b1.x, b1.y, b1.z, b1.w};
#pragma unroll
                for (int i = 0; i < 8; i++)
#pragma unroll
                    for (int j = 0; j < 8; j++)
                        acc[i][j] += a[i] * b[j];
            }
            __syncthreads();
        }
    }

    // epilogue: bias + relu
    float bj[8];
#pragma unroll
    for (int j = 0; j < 8; j++) bj[j] = bias[tn * 8 + j];

    if (!HEAD) {
#pragma unroll
        for (int i = 0; i < 8; i++) {
            int row = m0 + tm * 8 + i;
            if (row < M) {
                float4 o0, o1;
                o0.x = fmaxf(acc[i][0] + bj[0], 0.f);
                o0.y = fmaxf(acc[i][1] + bj[1], 0.f);
                o0.z = fmaxf(acc[i][2] + bj[2], 0.f);
                o0.w = fmaxf(acc[i][3] + bj[3], 0.f);
                o1.x = fmaxf(acc[i][4] + bj[4], 0.f);
                o1.y = fmaxf(acc[i][5] + bj[5], 0.f);
                o1.z = fmaxf(acc[i][6] + bj[6], 0.f);
                o1.w = fmaxf(acc[i][7] + bj[7], 0.f);
                float* yp = Y + (long long)row * HID + tn * 8;
                *reinterpret_cast<float4*>(yp)     = o0;
                *reinterpret_cast<float4*>(yp + 4) = o1;
            }
        }
    } else {
        // fused head: out[m] = sum_n relu(y)*Wprd[n] + bprd
        __shared__ float red[BM][17];
        float wp[8];
#pragma unroll
        for (int j = 0; j < 8; j++) wp[j] = Wprd[tn * 8 + j];
#pragma unroll
        for (int i = 0; i < 8; i++) {
            float p = 0.f;
#pragma unroll
            for (int j = 0; j < 8; j++)
                p += fmaxf(acc[i][j] + bj[j], 0.f) * wp[j];
            red[tm * 8 + i][tn] = p;
        }
        __syncthreads();
        if (tid < BM) {
            int row = m0 + tid;
            if (row < M) {
                float sum = 0.f;
#pragma unroll
                for (int t = 0; t < 16; t++) sum += red[tid][t];
                Y[row] = sum + bprd[0];
            }
        }
    }
}

// ---------------------------------------------------------------------------
extern "C" void kernel_launch(void* const* d_in, const int* in_sizes, int n_in,
                              void* d_out, int out_size) {
    const float* x     = (const float*)d_in[0];   // (N,1,64)
    const int*   ei    = (const int*)d_in[1];     // (2,E) int32
    const float* ew    = (const float*)d_in[2];   // (E,)
    const float* Wrel0 = (const float*)d_in[3];
    const float* brel0 = (const float*)d_in[4];
    const float* Wroot0= (const float*)d_in[5];
    const float* Wro0  = (const float*)d_in[6];
    const float* bro0  = (const float*)d_in[7];
    const float* Wrel1 = (const float*)d_in[8];
    const float* brel1 = (const float*)d_in[9];
    const float* Wroot1= (const float*)d_in[10];
    const float* Wro1  = (const float*)d_in[11];
    const float* bro1  = (const float*)d_in[12];
    const float* Wprd  = (const float*)d_in[13];
    const float* bprd  = (const float*)d_in[14];
    float*       out   = (float*)d_out;

    int N = in_sizes[0] / IN_CH;  // 50000
    int E = in_sizes[2];          // 800000

    float* agg; cudaGetSymbolAddress((void**)&agg, g_agg);
    float* h1;  cudaGetSymbolAddress((void**)&h1,  g_h1);
    float* h2;  cudaGetSymbolAddress((void**)&h2,  g_h2);

    int zt = 256;
    int gemm_blocks = (N + BM - 1) / BM;

    // --- layer 0 ---
    zero_cnt_agg64<<<(N * IN_CH + zt - 1) / zt, zt>>>(N);
    {
        long long total = (long long)E * 32;
        scatter64<<<(int)((total + 255) / 256), 256>>>(ei, ew, x, E);
    }
    inv_cnt<<<(N + zt - 1) / zt, zt>>>(N);
    scale_agg<IN_CH><<<(N * IN_CH + zt - 1) / zt, zt>>>(N);

    // conv0: h1 = relu(agg@Wrel0^T + brel0 + x@Wroot0^T)
    gemm_kernel<IN_CH, true, false><<<gemm_blocks, 256>>>(
        agg, Wrel0, x, Wroot0, brel0, nullptr, nullptr, h1, N);
    // ro0: h2 = relu(h1@Wro0^T + bro0)
    gemm_kernel<HID, false, false><<<gemm_blocks, 256>>>(
        h1, Wro0, nullptr, nullptr, bro0, nullptr, nullptr, h2, N);

    // --- layer 1 ---
    zero_agg128<<<(N * HID + zt - 1) / zt, zt>>>(N);
    {
        long long total = (long long)E * 32;
        scatter128<<<(int)((total + 255) / 256), 256>>>(ei, ew, h2, E);
    }
    scale_agg<HID><<<(N * HID + zt - 1) / zt, zt>>>(N);

    // conv1: h1 = relu(agg@Wrel1^T + brel1 + h2@Wroot1^T)
    gemm_kernel<HID, true, false><<<gemm_blocks, 256>>>(
        agg, Wrel1, h2, Wroot1, brel1, nullptr, nullptr, h1, N);

    // ro1 + head fused: out = relu(h1@Wro1^T + bro1) @ Wprd^T + bprd
    gemm_kernel<HID, false, true><<<gemm_blocks, 256>>>(
        h1, Wro1, nullptr, nullptr, bro1, Wprd, bprd, out, N);
}

// round 5
// speedup vs baseline: 12.5656x; 1.7142x over previous
#include <cuda_runtime.h>
#include <cstdint>

#define N_NODES 50000
#define IN_CH 64
#define HID 128
#define NTHREADS 256

// Scratch (device globals -- no allocation allowed)
__device__ float g_cnt[N_NODES];        // after inv_cnt: 1/max(count,1)
__device__ float g_agg[N_NODES * HID];
__device__ float g_h1[N_NODES * HID];
__device__ float g_h2[N_NODES * HID];

__device__ __forceinline__ float to_tf32(float x) {
    float y; asm("cvt.rna.tf32.f32 %0, %1;" : "=f"(y) : "f"(x)); return y;
}

__device__ __forceinline__ void mma_tf32(float c[4], const uint32_t a[4], const uint32_t b[2]) {
    asm volatile(
        "mma.sync.aligned.m16n8k8.row.col.f32.tf32.tf32.f32 "
        "{%0,%1,%2,%3}, {%4,%5,%6,%7}, {%8,%9}, {%0,%1,%2,%3};"
        : "+f"(c[0]), "+f"(c[1]), "+f"(c[2]), "+f"(c[3])
        : "r"(a[0]), "r"(a[1]), "r"(a[2]), "r"(a[3]), "r"(b[0]), "r"(b[1]));
}

// ---------------------------------------------------------------------------
// Zero / misc kernels
// ---------------------------------------------------------------------------
__global__ void zero_cnt_agg64(int n) {
    int i = blockIdx.x * blockDim.x + threadIdx.x;
    if (i < n * IN_CH) g_agg[i] = 0.0f;
    if (i < n)         g_cnt[i] = 0.0f;
}
__global__ void zero_agg128(int n) {
    int i = blockIdx.x * blockDim.x + threadIdx.x;
    if (i < n * HID) g_agg[i] = 0.0f;
}
__global__ void inv_cnt(int n) {
    int i = blockIdx.x * blockDim.x + threadIdx.x;
    if (i < n) g_cnt[i] = 1.0f / fmaxf(g_cnt[i], 1.0f);
}

// ---------------------------------------------------------------------------
// Scatter: one warp per edge (proven)
// ---------------------------------------------------------------------------
__global__ void scatter64(const int* __restrict__ ei, const float* __restrict__ ew,
                          const float* __restrict__ h, int E) {
    int gid = blockIdx.x * blockDim.x + threadIdx.x;
    int e = gid >> 5;
    if (e >= E) return;
    int lane = gid & 31;
    int src = ei[e], dst = ei[E + e];
    float w = ew[e];
    float2 v = reinterpret_cast<const float2*>(h + (size_t)src * IN_CH)[lane];
    v.x *= w; v.y *= w;
    atomicAdd(reinterpret_cast<float2*>(&g_agg[(size_t)dst * IN_CH]) + lane, v);
    if (lane == 0) atomicAdd(&g_cnt[dst], 1.0f);
}
__global__ void scatter128(const int* __restrict__ ei, const float* __restrict__ ew,
                           const float* __restrict__ h, int E) {
    int gid = blockIdx.x * blockDim.x + threadIdx.x;
    int e = gid >> 5;
    if (e >= E) return;
    int lane = gid & 31;
    int src = ei[e], dst = ei[E + e];
    float w = ew[e];
    float4 v = reinterpret_cast<const float4*>(h + (size_t)src * HID)[lane];
    v.x *= w; v.y *= w; v.z *= w; v.w *= w;
    atomicAdd(reinterpret_cast<float4*>(&g_agg[(size_t)dst * HID]) + lane, v);
}

// ---------------------------------------------------------------------------
// mma.sync tf32 GEMM: Y[Mx128] = act( A1@B1^T (+ A2@B2^T) + bias )
//   CTA: 128 rows x 128 cols, 8 warps (4x2), warp tile 32x64 (2x8 m16n8k8).
//   A: [M x KT] node features (row-major); B: [128 x KT] weights (out x in).
//   SCALE: multiply A1 rows by cntinv[row] during smem load.
//   HEAD:  out[m] = sum_n relu(y[m,n]) * Wprd[n] + bprd
//   smem: As[128][KT+4], Bs[128][KT+4] (Bs rows = output channel n).
//   Fragment loads are scalar LDS, conflict-free by stride (KT+4)%32==4.
// ---------------------------------------------------------------------------
template <int KT, bool DUAL, bool SCALE, bool HEAD>
__global__ void __launch_bounds__(NTHREADS)
mma_gemm(const float* __restrict__ A1, const float* __restrict__ B1,
         const float* __restrict__ A2, const float* __restrict__ B2,
         const float* __restrict__ bias, const float* __restrict__ cntinv,
         const float* __restrict__ Wprd, const float* __restrict__ bprd,
         float* __restrict__ Y, int M)
{
    constexpr int S = KT + 4;                 // padded row stride (floats)
    extern __shared__ float sm[];
    float* As = sm;                            // [128][S]
    float* Bs = sm + 128 * S;                  // [128][S]
    __shared__ float red[128][2];

    int tid  = threadIdx.x;
    int lane = tid & 31;
    int warp = tid >> 5;
    int wm   = (warp >> 1) * 32;               // warp row base
    int wn   = (warp & 1) * 64;                // warp col base
    int gr   = lane >> 2;                      // 0..7
    int gc   = lane & 3;                       // 0..3
    int m0   = blockIdx.x * 128;

    float c[2][8][4];
#pragma unroll
    for (int mt = 0; mt < 2; mt++)
#pragma unroll
        for (int nt = 0; nt < 8; nt++)
#pragma unroll
            for (int j = 0; j < 4; j++) c[mt][nt][j] = 0.0f;

    const int NPH = DUAL ? 2 : 1;
    for (int ph = 0; ph < NPH; ph++) {
        const float* A = (DUAL && ph) ? A2 : A1;
        const float* B = (DUAL && ph) ? B2 : B1;
        if (ph) __syncthreads();               // protect smem reuse

        constexpr int C4 = KT / 4;
        constexpr int NQ = (128 * C4) / NTHREADS;
#pragma unroll
        for (int q = 0; q < NQ; q++) {
            int id  = tid + NTHREADS * q;
            int row = id / C4;
            int k   = (id % C4) * 4;

            float4 va = make_float4(0.f, 0.f, 0.f, 0.f);
            int grow = m0 + row;
            if (grow < M) {
                va = *reinterpret_cast<const float4*>(A + (size_t)grow * KT + k);
                if (SCALE && ph == 0) {
                    float s = cntinv[grow];
                    va.x *= s; va.y *= s; va.z *= s; va.w *= s;
                }
            }
            va.x = to_tf32(va.x); va.y = to_tf32(va.y);
            va.z = to_tf32(va.z); va.w = to_tf32(va.w);
            *reinterpret_cast<float4*>(As + row * S + k) = va;

            float4 vb = *reinterpret_cast<const float4*>(B + (size_t)row * KT + k);
            vb.x = to_tf32(vb.x); vb.y = to_tf32(vb.y);
            vb.z = to_tf32(vb.z); vb.w = to_tf32(vb.w);
            *reinterpret_cast<float4*>(Bs + row * S + k) = vb;
        }
        __syncthreads();

        const uint32_t* Au = reinterpret_cast<const uint32_t*>(As);
        const uint32_t* Bu = reinterpret_cast<const uint32_t*>(Bs);

#pragma unroll
        for (int k0 = 0; k0 < KT; k0 += 8) {
            uint32_t a[2][4];
#pragma unroll
            for (int mt = 0; mt < 2; mt++) {
                int rlo = wm + mt * 16 + gr;
                a[mt][0] = Au[rlo * S + k0 + gc];
                a[mt][1] = Au[(rlo + 8) * S + k0 + gc];
                a[mt][2] = Au[rlo * S + k0 + gc + 4];
                a[mt][3] = Au[(rlo + 8) * S + k0 + gc + 4];
            }
            uint32_t b[8][2];
#pragma unroll
            for (int nt = 0; nt < 8; nt++) {
                int col = wn + nt * 8 + gr;    // output channel n
                b[nt][0] = Bu[col * S + k0 + gc];
                b[nt][1] = Bu[col * S + k0 + gc + 4];
            }
#pragma unroll
            for (int mt = 0; mt < 2; mt++)
#pragma unroll
                for (int nt = 0; nt < 8; nt++)
                    mma_tf32(c[mt][nt], a[mt], b[nt]);
        }
    }

    // --- epilogue ---
    if (!HEAD) {
#pragma unroll
        for (int mt = 0; mt < 2; mt++) {
            int rlo = m0 + wm + mt * 16 + gr;
            int rhi = rlo + 8;
#pragma unroll
            for (int nt = 0; nt < 8; nt++) {
                int col = wn + nt * 8 + 2 * gc;
                float b0 = bias[col], b1 = bias[col + 1];
                if (rlo < M) {
                    float2 o;
                    o.x = fmaxf(c[mt][nt][0] + b0, 0.f);
                    o.y = fmaxf(c[mt][nt][1] + b1, 0.f);
                    *reinterpret_cast<float2*>(Y + (size_t)rlo * HID + col) = o;
                }
                if (rhi < M) {
                    float2 o;
                    o.x = fmaxf(c[mt][nt][2] + b0, 0.f);
                    o.y = fmaxf(c[mt][nt][3] + b1, 0.f);
                    *reinterpret_cast<float2*>(Y + (size_t)rhi * HID + col) = o;
                }
            }
        }
    } else {
#pragma unroll
        for (int mt = 0; mt < 2; mt++) {
            float plo = 0.f, phi = 0.f;
#pragma unroll
            for (int nt = 0; nt < 8; nt++) {
                int col = wn + nt * 8 + 2 * gc;
                float b0 = bias[col], b1 = bias[col + 1];
                float w0 = Wprd[col], w1 = Wprd[col + 1];
                plo += fmaxf(c[mt][nt][0] + b0, 0.f) * w0 +
                       fmaxf(c[mt][nt][1] + b1, 0.f) * w1;
                phi += fmaxf(c[mt][nt][2] + b0, 0.f) * w0 +
                       fmaxf(c[mt][nt][3] + b1, 0.f) * w1;
            }
            // reduce over the 4 lanes sharing a row (gc = 0..3)
            plo += __shfl_xor_sync(0xFFFFFFFFu, plo, 1);
            plo += __shfl_xor_sync(0xFFFFFFFFu, plo, 2);
            phi += __shfl_xor_sync(0xFFFFFFFFu, phi, 1);
            phi += __shfl_xor_sync(0xFFFFFFFFu, phi, 2);
            if (gc == 0) {
                red[wm + mt * 16 + gr][warp & 1]     = plo;
                red[wm + mt * 16 + gr + 8][warp & 1] = phi;
            }
        }
        __syncthreads();
        if (tid < 128) {
            int row = m0 + tid;
            if (row < M) Y[row] = red[tid][0] + red[tid][1] + bprd[0];
        }
    }
}

// ---------------------------------------------------------------------------
#define SMEM_K128 (2 * 128 * (128 + 4) * 4)
#define SMEM_K64  (2 * 128 * (64 + 4) * 4)

extern "C" void kernel_launch(void* const* d_in, const int* in_sizes, int n_in,
                              void* d_out, int out_size) {
    const float* x     = (const float*)d_in[0];   // (N,1,64)
    const int*   ei    = (const int*)d_in[1];     // (2,E) int32
    const float* ew    = (const float*)d_in[2];
    const float* Wrel0 = (const float*)d_in[3];
    const float* brel0 = (const float*)d_in[4];
    const float* Wroot0= (const float*)d_in[5];
    const float* Wro0  = (const float*)d_in[6];
    const float* bro0  = (const float*)d_in[7];
    const float* Wrel1 = (const float*)d_in[8];
    const float* brel1 = (const float*)d_in[9];
    const float* Wroot1= (const float*)d_in[10];
    const float* Wro1  = (const float*)d_in[11];
    const float* bro1  = (const float*)d_in[12];
    const float* Wprd  = (const float*)d_in[13];
    const float* bprd  = (const float*)d_in[14];
    float*       out   = (float*)d_out;

    int N = in_sizes[0] / IN_CH;  // 50000
    int E = in_sizes[2];          // 800000

    float* agg; cudaGetSymbolAddress((void**)&agg, g_agg);
    float* cnt; cudaGetSymbolAddress((void**)&cnt, g_cnt);
    float* h1;  cudaGetSymbolAddress((void**)&h1,  g_h1);
    float* h2;  cudaGetSymbolAddress((void**)&h2,  g_h2);

    cudaFuncSetAttribute(mma_gemm<IN_CH, true,  true,  false>, cudaFuncAttributeMaxDynamicSharedMemorySize, SMEM_K64);
    cudaFuncSetAttribute(mma_gemm<HID,   false, false, false>, cudaFuncAttributeMaxDynamicSharedMemorySize, SMEM_K128);
    cudaFuncSetAttribute(mma_gemm<HID,   true,  true,  false>, cudaFuncAttributeMaxDynamicSharedMemorySize, SMEM_K128);
    cudaFuncSetAttribute(mma_gemm<HID,   false, false, true >, cudaFuncAttributeMaxDynamicSharedMemorySize, SMEM_K128);

    int zt = 256;
    int gb = (N + 127) / 128;

    // --- layer 0 ---
    zero_cnt_agg64<<<(N * IN_CH + zt - 1) / zt, zt>>>(N);
    {
        long long total = (long long)E * 32;
        scatter64<<<(int)((total + 255) / 256), 256>>>(ei, ew, x, E);
    }
    inv_cnt<<<(N + zt - 1) / zt, zt>>>(N);

    // conv0: h1 = relu( (agg*inv)@Wrel0^T + brel0 + x@Wroot0^T )
    mma_gemm<IN_CH, true, true, false><<<gb, NTHREADS, SMEM_K64>>>(
        agg, Wrel0, x, Wroot0, brel0, cnt, nullptr, nullptr, h1, N);
    // ro0: h2 = relu(h1@Wro0^T + bro0)
    mma_gemm<HID, false, false, false><<<gb, NTHREADS, SMEM_K128>>>(
        h1, Wro0, nullptr, nullptr, bro0, nullptr, nullptr, nullptr, h2, N);

    // --- layer 1 ---
    zero_agg128<<<(N * HID + zt - 1) / zt, zt>>>(N);
    {
        long long total = (long long)E * 32;
        scatter128<<<(int)((total + 255) / 256), 256>>>(ei, ew, h2, E);
    }
    // conv1: h1 = relu( (agg*inv)@Wrel1^T + brel1 + h2@Wroot1^T )
    mma_gemm<HID, true, true, false><<<gb, NTHREADS, SMEM_K128>>>(
        agg, Wrel1, h2, Wroot1, brel1, cnt, nullptr, nullptr, h1, N);

    // ro1 + head fused: out = relu(h1@Wro1^T + bro1) @ Wprd^T + bprd
    mma_gemm<HID, false, false, true><<<gb, NTHREADS, SMEM_K128>>>(
        h1, Wro1, nullptr, nullptr, bro1, nullptr, Wprd, bprd, out, N);
}

// round 6
// speedup vs baseline: 13.9247x; 1.1082x over previous
#include <cuda_runtime.h>
#include <cstdint>

#define N_NODES 50000
#define N_EDGES 800000
#define IN_CH 64
#define HID 128
#define NTHREADS 256

// Scratch (device globals -- no allocation allowed)
__device__ int   g_deg[N_NODES];
__device__ int   g_off[N_NODES];
__device__ int   g_cur[N_NODES];
__device__ int   g_part[64];
__device__ int   g_esrc[N_EDGES];
__device__ float g_ew[N_EDGES];
__device__ float g_agg[N_NODES * HID];
__device__ float g_h1[N_NODES * HID];
__device__ float g_h2[N_NODES * HID];

__device__ __forceinline__ float to_tf32(float x) {
    float y; asm("cvt.rna.tf32.f32 %0, %1;" : "=f"(y) : "f"(x)); return y;
}
__device__ __forceinline__ void split_tf32(float v, uint32_t& hi, uint32_t& lo) {
    float h = to_tf32(v);
    float l = to_tf32(v - h);
    hi = __float_as_uint(h);
    lo = __float_as_uint(l);
}
__device__ __forceinline__ void mma_tf32(float c[4], const uint32_t a[4], const uint32_t b[2]) {
    asm volatile(
        "mma.sync.aligned.m16n8k8.row.col.f32.tf32.tf32.f32 "
        "{%0,%1,%2,%3}, {%4,%5,%6,%7}, {%8,%9}, {%0,%1,%2,%3};"
        : "+f"(c[0]), "+f"(c[1]), "+f"(c[2]), "+f"(c[3])
        : "r"(a[0]), "r"(a[1]), "r"(a[2]), "r"(a[3]), "r"(b[0]), "r"(b[1]));
}

// ---------------------------------------------------------------------------
// CSR build: histogram -> scan -> fill
// ---------------------------------------------------------------------------
__global__ void zero_deg(int n) {
    int i = blockIdx.x * blockDim.x + threadIdx.x;
    if (i < n) g_deg[i] = 0;
}
__global__ void hist(const int* __restrict__ ei, int E) {
    int e = blockIdx.x * blockDim.x + threadIdx.x;
    if (e < E) atomicAdd(&g_deg[ei[E + e]], 1);
}
// block-level exclusive scan (1024/block), partial totals to g_part
__global__ void scan1(int n) {
    __shared__ int s[1024];
    int tid = threadIdx.x;
    int i = blockIdx.x * 1024 + tid;
    int v = (i < n) ? g_deg[i] : 0;
    s[tid] = v;
    __syncthreads();
    for (int off = 1; off < 1024; off <<= 1) {
        int t = (tid >= off) ? s[tid - off] : 0;
        __syncthreads();
        s[tid] += t;
        __syncthreads();
    }
    if (i < n) g_off[i] = s[tid] - v;   // exclusive
    if (tid == 1023) g_part[blockIdx.x] = s[1023];
}
__global__ void scan2(int nb) {
    if (threadIdx.x == 0) {
        int run = 0;
        for (int b = 0; b < nb; b++) { int t = g_part[b]; g_part[b] = run; run += t; }
    }
}
__global__ void scan3(int n) {
    int i = blockIdx.x * blockDim.x + threadIdx.x;
    if (i < n) {
        int o = g_off[i] + g_part[i >> 10];
        g_off[i] = o;
        g_cur[i] = o;
    }
}
__global__ void fill(const int* __restrict__ ei, const float* __restrict__ ew, int E) {
    int e = blockIdx.x * blockDim.x + threadIdx.x;
    if (e >= E) return;
    int dst = ei[E + e];
    int p = atomicAdd(&g_cur[dst], 1);
    g_esrc[p] = ei[e];
    g_ew[p]   = ew[e];
}

// ---------------------------------------------------------------------------
// Gather: one warp per dst node; agg[n] = (sum_e w_e * h[src_e]) / max(deg,1)
// ---------------------------------------------------------------------------
__global__ void gather64(const float* __restrict__ h, int N) {
    int warp = (blockIdx.x * blockDim.x + threadIdx.x) >> 5;
    int lane = threadIdx.x & 31;
    if (warp >= N) return;
    int start = g_off[warp];
    int d = g_deg[warp];
    float2 acc = make_float2(0.f, 0.f);
    for (int base = 0; base < d; base += 32) {
        int m = min(32, d - base);
        int s = 0; float w = 0.f;
        if (lane < m) { s = g_esrc[start + base + lane]; w = g_ew[start + base + lane]; }
        for (int j = 0; j < m; j++) {
            int sj = __shfl_sync(0xFFFFFFFFu, s, j);
            float wj = __shfl_sync(0xFFFFFFFFu, w, j);
            float2 v = reinterpret_cast<const float2*>(h + (size_t)sj * IN_CH)[lane];
            acc.x += wj * v.x;
            acc.y += wj * v.y;
        }
    }
    float inv = 1.0f / fmaxf((float)d, 1.0f);
    reinterpret_cast<float2*>(g_agg + (size_t)warp * IN_CH)[lane] =
        make_float2(acc.x * inv, acc.y * inv);
}

__global__ void gather128(const float* __restrict__ h, int N) {
    int warp = (blockIdx.x * blockDim.x + threadIdx.x) >> 5;
    int lane = threadIdx.x & 31;
    if (warp >= N) return;
    int start = g_off[warp];
    int d = g_deg[warp];
    float4 acc = make_float4(0.f, 0.f, 0.f, 0.f);
    for (int base = 0; base < d; base += 32) {
        int m = min(32, d - base);
        int s = 0; float w = 0.f;
        if (lane < m) { s = g_esrc[start + base + lane]; w = g_ew[start + base + lane]; }
        for (int j = 0; j < m; j++) {
            int sj = __shfl_sync(0xFFFFFFFFu, s, j);
            float wj = __shfl_sync(0xFFFFFFFFu, w, j);
            float4 v = reinterpret_cast<const float4*>(h + (size_t)sj * HID)[lane];
            acc.x += wj * v.x; acc.y += wj * v.y;
            acc.z += wj * v.z; acc.w += wj * v.w;
        }
    }
    float inv = 1.0f / fmaxf((float)d, 1.0f);
    reinterpret_cast<float4*>(g_agg + (size_t)warp * HID)[lane] =
        make_float4(acc.x * inv, acc.y * inv, acc.z * inv, acc.w * inv);
}

// ---------------------------------------------------------------------------
// 3xTF32 mma GEMM: Y[Mx128] = act( A1@B1^T (+ A2@B2^T) + bias )
//   CTA 128x128, 8 warps (4x2), warp tile 32x64 (2x8 m16n8k8).
//   K processed in chunks of 64 (smem 68KB -> 2 CTA/SM).
//   smem holds fp32; hi/lo tf32 split computed at fragment load.
//   HEAD: out[m] = sum_n relu(y[m,n]) * Wprd[n] + bprd
// ---------------------------------------------------------------------------
#define KC 64
#define SS (KC + 4)

template <int KT, bool DUAL, bool HEAD>
__global__ void __launch_bounds__(NTHREADS, 2)
mma_gemm(const float* __restrict__ A1, const float* __restrict__ B1,
         const float* __restrict__ A2, const float* __restrict__ B2,
         const float* __restrict__ bias,
         const float* __restrict__ Wprd, const float* __restrict__ bprd,
         float* __restrict__ Y, int M)
{
    extern __shared__ float sm[];
    float* As = sm;               // [128][SS]
    float* Bs = sm + 128 * SS;    // [128][SS]
    __shared__ float red[128][2];

    int tid  = threadIdx.x;
    int lane = tid & 31;
    int warp = tid >> 5;
    int wm   = (warp >> 1) * 32;
    int wn   = (warp & 1) * 64;
    int gr   = lane >> 2;
    int gc   = lane & 3;
    int m0   = blockIdx.x * 128;

    float c[2][8][4];
#pragma unroll
    for (int mt = 0; mt < 2; mt++)
#pragma unroll
        for (int nt = 0; nt < 8; nt++)
#pragma unroll
            for (int j = 0; j < 4; j++) c[mt][nt][j] = 0.0f;

    constexpr int NCH = KT / KC;
    const int NPH = (DUAL ? 2 : 1) * NCH;

    for (int ph = 0; ph < NPH; ph++) {
        int srcidx = ph / NCH;
        int ch     = ph % NCH;
        const float* A = (DUAL && srcidx) ? A2 : A1;
        const float* B = (DUAL && srcidx) ? B2 : B1;
        if (ph) __syncthreads();

        // load 128x64 fp32 tiles (8 float4 per thread per tile)
#pragma unroll
        for (int q = 0; q < (128 * (KC / 4)) / NTHREADS; q++) {
            int id  = tid + NTHREADS * q;
            int row = id >> 4;           // /16 float4 per row
            int k   = (id & 15) * 4;
            int grow = m0 + row;
            float4 va = make_float4(0.f, 0.f, 0.f, 0.f);
            if (grow < M)
                va = *reinterpret_cast<const float4*>(A + (size_t)grow * KT + ch * KC + k);
            *reinterpret_cast<float4*>(As + row * SS + k) = va;
            float4 vb = *reinterpret_cast<const float4*>(B + (size_t)row * KT + ch * KC + k);
            *reinterpret_cast<float4*>(Bs + row * SS + k) = vb;
        }
        __syncthreads();

#pragma unroll
        for (int k0 = 0; k0 < KC; k0 += 8) {
            uint32_t ah[2][4], al[2][4];
#pragma unroll
            for (int mt = 0; mt < 2; mt++) {
                int rlo = wm + mt * 16 + gr;
                split_tf32(As[rlo * SS + k0 + gc],           ah[mt][0], al[mt][0]);
                split_tf32(As[(rlo + 8) * SS + k0 + gc],     ah[mt][1], al[mt][1]);
                split_tf32(As[rlo * SS + k0 + gc + 4],       ah[mt][2], al[mt][2]);
                split_tf32(As[(rlo + 8) * SS + k0 + gc + 4], ah[mt][3], al[mt][3]);
            }
#pragma unroll
            for (int nt = 0; nt < 8; nt++) {
                int col = wn + nt * 8 + gr;
                uint32_t bh[2], bl[2];
                split_tf32(Bs[col * SS + k0 + gc],     bh[0], bl[0]);
                split_tf32(Bs[col * SS + k0 + gc + 4], bh[1], bl[1]);
#pragma unroll
                for (int mt = 0; mt < 2; mt++) {
                    mma_tf32(c[mt][nt], ah[mt], bl);
                    mma_tf32(c[mt][nt], al[mt], bh);
                    mma_tf32(c[mt][nt], ah[mt], bh);
                }
            }
        }
    }

    // --- epilogue ---
    if (!HEAD) {
#pragma unroll
        for (int mt = 0; mt < 2; mt++) {
            int rlo = m0 + wm + mt * 16 + gr;
            int rhi = rlo + 8;
#pragma unroll
            for (int nt = 0; nt < 8; nt++) {
                int col = wn + nt * 8 + 2 * gc;
                float b0 = bias[col], b1 = bias[col + 1];
                if (rlo < M) {
                    float2 o;
                    o.x = fmaxf(c[mt][nt][0] + b0, 0.f);
                    o.y = fmaxf(c[mt][nt][1] + b1, 0.f);
                    *reinterpret_cast<float2*>(Y + (size_t)rlo * HID + col) = o;
                }
                if (rhi < M) {
                    float2 o;
                    o.x = fmaxf(c[mt][nt][2] + b0, 0.f);
                    o.y = fmaxf(c[mt][nt][3] + b1, 0.f);
                    *reinterpret_cast<float2*>(Y + (size_t)rhi * HID + col) = o;
                }
            }
        }
    } else {
#pragma unroll
        for (int mt = 0; mt < 2; mt++) {
            float plo = 0.f, phi = 0.f;
#pragma unroll
            for (int nt = 0; nt < 8; nt++) {
                int col = wn + nt * 8 + 2 * gc;
                float b0 = bias[col], b1 = bias[col + 1];
                float w0 = Wprd[col], w1 = Wprd[col + 1];
                plo += fmaxf(c[mt][nt][0] + b0, 0.f) * w0 +
                       fmaxf(c[mt][nt][1] + b1, 0.f) * w1;
                phi += fmaxf(c[mt][nt][2] + b0, 0.f) * w0 +
                       fmaxf(c[mt][nt][3] + b1, 0.f) * w1;
            }
            plo += __shfl_xor_sync(0xFFFFFFFFu, plo, 1);
            plo += __shfl_xor_sync(0xFFFFFFFFu, plo, 2);
            phi += __shfl_xor_sync(0xFFFFFFFFu, phi, 1);
            phi += __shfl_xor_sync(0xFFFFFFFFu, phi, 2);
            if (gc == 0) {
                red[wm + mt * 16 + gr][warp & 1]     = plo;
                red[wm + mt * 16 + gr + 8][warp & 1] = phi;
            }
        }
        __syncthreads();
        if (tid < 128) {
            int row = m0 + tid;
            if (row < M) Y[row] = red[tid][0] + red[tid][1] + bprd[0];
        }
    }
}

// ---------------------------------------------------------------------------
#define GEMM_SMEM (2 * 128 * SS * 4)

extern "C" void kernel_launch(void* const* d_in, const int* in_sizes, int n_in,
                              void* d_out, int out_size) {
    const float* x     = (const float*)d_in[0];   // (N,1,64)
    const int*   ei    = (const int*)d_in[1];     // (2,E) int32
    const float* ew    = (const float*)d_in[2];
    const float* Wrel0 = (const float*)d_in[3];
    const float* brel0 = (const float*)d_in[4];
    const float* Wroot0= (const float*)d_in[5];
    const float* Wro0  = (const float*)d_in[6];
    const float* bro0  = (const float*)d_in[7];
    const float* Wrel1 = (const float*)d_in[8];
    const float* brel1 = (const float*)d_in[9];
    const float* Wroot1= (const float*)d_in[10];
    const float* Wro1  = (const float*)d_in[11];
    const float* bro1  = (const float*)d_in[12];
    const float* Wprd  = (const float*)d_in[13];
    const float* bprd  = (const float*)d_in[14];
    float*       out   = (float*)d_out;

    int N = in_sizes[0] / IN_CH;  // 50000
    int E = in_sizes[2];          // 800000

    float* agg; cudaGetSymbolAddress((void**)&agg, g_agg);
    float* h1;  cudaGetSymbolAddress((void**)&h1,  g_h1);
    float* h2;  cudaGetSymbolAddress((void**)&h2,  g_h2);

    cudaFuncSetAttribute(mma_gemm<IN_CH, true,  false>, cudaFuncAttributeMaxDynamicSharedMemorySize, GEMM_SMEM);
    cudaFuncSetAttribute(mma_gemm<HID,   false, false>, cudaFuncAttributeMaxDynamicSharedMemorySize, GEMM_SMEM);
    cudaFuncSetAttribute(mma_gemm<HID,   true,  false>, cudaFuncAttributeMaxDynamicSharedMemorySize, GEMM_SMEM);
    cudaFuncSetAttribute(mma_gemm<HID,   false, true >, cudaFuncAttributeMaxDynamicSharedMemorySize, GEMM_SMEM);

    int gb = (N + 127) / 128;
    int nb_scan = (N + 1023) / 1024;

    // --- CSR build (shared by both layers) ---
    zero_deg<<<(N + 255) / 256, 256>>>(N);
    hist<<<(E + 255) / 256, 256>>>(ei, E);
    scan1<<<nb_scan, 1024>>>(N);
    scan2<<<1, 32>>>(nb_scan);
    scan3<<<(N + 255) / 256, 256>>>(N);
    fill<<<(E + 255) / 256, 256>>>(ei, ew, E);

    // --- layer 0 ---
    gather64<<<(N * 32 + 255) / 256, 256>>>(x, N);
    mma_gemm<IN_CH, true, false><<<gb, NTHREADS, GEMM_SMEM>>>(
        agg, Wrel0, x, Wroot0, brel0, nullptr, nullptr, h1, N);
    mma_gemm<HID, false, false><<<gb, NTHREADS, GEMM_SMEM>>>(
        h1, Wro0, nullptr, nullptr, bro0, nullptr, nullptr, h2, N);

    // --- layer 1 ---
    gather128<<<(N * 32 + 255) / 256, 256>>>(h2, N);
    mma_gemm<HID, true, false><<<gb, NTHREADS, GEMM_SMEM>>>(
        agg, Wrel1, h2, Wroot1, brel1, nullptr, nullptr, h1, N);

    // ro1 + head fused
    mma_gemm<HID, false, true><<<gb, NTHREADS, GEMM_SMEM>>>(
        h1, Wro1, nullptr, nullptr, bro1, Wprd, bprd, out, N);
}

// round 7
// speedup vs baseline: 14.1317x; 1.0149x over previous
#include <cuda_runtime.h>
#include <cuda_bf16.h>
#include <cstdint>

#define N_NODES 50000
#define N_EDGES 800000
#define IN_CH 64
#define HID 128
#define NTHREADS 256

// Scratch (device globals -- no allocation allowed)
__device__ int   g_deg[N_NODES];
__device__ int   g_off[N_NODES];
__device__ int   g_cur[N_NODES];
__device__ int   g_esrc[N_EDGES];
__device__ float g_ew[N_EDGES];
__device__ float g_agg[N_NODES * HID];
__device__ float g_h1[N_NODES * HID];
__device__ float g_h2[N_NODES * HID];

// ---------------------------------------------------------------------------
// bf16 helpers
// ---------------------------------------------------------------------------
__device__ __forceinline__ uint32_t pack_bf2(float a, float b) {
    __nv_bfloat162 t = __floats2bfloat162_rn(a, b);
    return *reinterpret_cast<uint32_t*>(&t);
}
// split (a,b) into hi/lo bf16 pairs
__device__ __forceinline__ void split_bf2(float a, float b, uint32_t& hi, uint32_t& lo) {
    float ah = __bfloat162float(__float2bfloat16_rn(a));
    float bh = __bfloat162float(__float2bfloat16_rn(b));
    hi = pack_bf2(ah, bh);
    lo = pack_bf2(a - ah, b - bh);
}
__device__ __forceinline__ void mma_bf16(float c[4], const uint32_t a[4], const uint32_t b[2]) {
    asm volatile(
        "mma.sync.aligned.m16n8k16.row.col.f32.bf16.bf16.f32 "
        "{%0,%1,%2,%3}, {%4,%5,%6,%7}, {%8,%9}, {%0,%1,%2,%3};"
        : "+f"(c[0]), "+f"(c[1]), "+f"(c[2]), "+f"(c[3])
        : "r"(a[0]), "r"(a[1]), "r"(a[2]), "r"(a[3]), "r"(b[0]), "r"(b[1]));
}

// ---------------------------------------------------------------------------
// CSR build: histogram -> single-block scan -> fill
// ---------------------------------------------------------------------------
__global__ void zero_deg(int n) {
    int i = blockIdx.x * blockDim.x + threadIdx.x;
    if (i < n) g_deg[i] = 0;
}
__global__ void hist(const int* __restrict__ ei, int E) {
    int e = blockIdx.x * blockDim.x + threadIdx.x;
    if (e < E) atomicAdd(&g_deg[ei[E + e]], 1);
}
// one block, 1024 threads: full exclusive scan of g_deg -> g_off / g_cur
__global__ void scan_all(int n) {
    __shared__ int s[1024];
    int tid = threadIdx.x;
    int per = (n + 1023) >> 10;
    int lo = tid * per;
    int hi = min(lo + per, n);
    int sum = 0;
    for (int i = lo; i < hi; i++) sum += g_deg[i];
    s[tid] = sum;
    __syncthreads();
    for (int off = 1; off < 1024; off <<= 1) {
        int t = (tid >= off) ? s[tid - off] : 0;
        __syncthreads();
        s[tid] += t;
        __syncthreads();
    }
    int run = tid ? s[tid - 1] : 0;
    for (int i = lo; i < hi; i++) {
        g_off[i] = run;
        g_cur[i] = run;
        run += g_deg[i];
    }
}
__global__ void fill(const int* __restrict__ ei, const float* __restrict__ ew, int E) {
    int e = blockIdx.x * blockDim.x + threadIdx.x;
    if (e >= E) return;
    int dst = ei[E + e];
    int p = atomicAdd(&g_cur[dst], 1);
    g_esrc[p] = ei[e];
    g_ew[p]   = ew[e];
}

// ---------------------------------------------------------------------------
// Gather: one warp per dst node; agg[n] = (sum_e w_e * h[src_e]) / max(deg,1)
// ---------------------------------------------------------------------------
__global__ void gather64(const float* __restrict__ h, int N) {
    int warp = (blockIdx.x * blockDim.x + threadIdx.x) >> 5;
    int lane = threadIdx.x & 31;
    if (warp >= N) return;
    int start = g_off[warp];
    int d = g_deg[warp];
    float2 acc = make_float2(0.f, 0.f);
    for (int base = 0; base < d; base += 32) {
        int m = min(32, d - base);
        int s = 0; float w = 0.f;
        if (lane < m) { s = g_esrc[start + base + lane]; w = g_ew[start + base + lane]; }
        for (int j = 0; j < m; j++) {
            int sj = __shfl_sync(0xFFFFFFFFu, s, j);
            float wj = __shfl_sync(0xFFFFFFFFu, w, j);
            float2 v = reinterpret_cast<const float2*>(h + (size_t)sj * IN_CH)[lane];
            acc.x += wj * v.x;
            acc.y += wj * v.y;
        }
    }
    float inv = 1.0f / fmaxf((float)d, 1.0f);
    reinterpret_cast<float2*>(g_agg + (size_t)warp * IN_CH)[lane] =
        make_float2(acc.x * inv, acc.y * inv);
}

__global__ void gather128(const float* __restrict__ h, int N) {
    int warp = (blockIdx.x * blockDim.x + threadIdx.x) >> 5;
    int lane = threadIdx.x & 31;
    if (warp >= N) return;
    int start = g_off[warp];
    int d = g_deg[warp];
    float4 acc = make_float4(0.f, 0.f, 0.f, 0.f);
    for (int base = 0; base < d; base += 32) {
        int m = min(32, d - base);
        int s = 0; float w = 0.f;
        if (lane < m) { s = g_esrc[start + base + lane]; w = g_ew[start + base + lane]; }
        for (int j = 0; j < m; j++) {
            int sj = __shfl_sync(0xFFFFFFFFu, s, j);
            float wj = __shfl_sync(0xFFFFFFFFu, w, j);
            float4 v = reinterpret_cast<const float4*>(h + (size_t)sj * HID)[lane];
            acc.x += wj * v.x; acc.y += wj * v.y;
            acc.z += wj * v.z; acc.w += wj * v.w;
        }
    }
    float inv = 1.0f / fmaxf((float)d, 1.0f);
    reinterpret_cast<float4*>(g_agg + (size_t)warp * HID)[lane] =
        make_float4(acc.x * inv, acc.y * inv, acc.z * inv, acc.w * inv);
}

// ---------------------------------------------------------------------------
// 3xBF16 mma GEMM: Y[Mx128] = act( A1@B1^T (+ A2@B2^T) + bias )
//   CTA 128x128, 8 warps (4x2), warp tile 32x64 (2x8 m16n8k16).
//   K processed in chunks of 64. smem holds hi/lo bf16x2 tiles,
//   row stride 36 words -> fragment loads conflict-free (bank = 4*gr+gc).
//   c += ah*bh + ah*bl + al*bh  (3-term bf16 split, ~1e-5 rel err)
//   HEAD: out[m] = sum_n relu(y[m,n]) * Wprd[n] + bprd
// ---------------------------------------------------------------------------
#define KC 64
#define SW 36           // words (bf16x2) per row: KC/2 + 4

template <int KT, bool DUAL, bool HEAD>
__global__ void __launch_bounds__(NTHREADS, 2)
mma_gemm(const float* __restrict__ A1, const float* __restrict__ B1,
         const float* __restrict__ A2, const float* __restrict__ B2,
         const float* __restrict__ bias,
         const float* __restrict__ Wprd, const float* __restrict__ bprd,
         float* __restrict__ Y, int M)
{
    extern __shared__ uint32_t sm[];
    uint32_t* AsH = sm;                 // [128][SW]
    uint32_t* AsL = sm + 128 * SW;
    uint32_t* BsH = sm + 2 * 128 * SW;
    uint32_t* BsL = sm + 3 * 128 * SW;
    __shared__ float red[128][2];

    int tid  = threadIdx.x;
    int lane = tid & 31;
    int warp = tid >> 5;
    int wm   = (warp >> 1) * 32;
    int wn   = (warp & 1) * 64;
    int gr   = lane >> 2;
    int gc   = lane & 3;
    int m0   = blockIdx.x * 128;

    float c[2][8][4];
#pragma unroll
    for (int mt = 0; mt < 2; mt++)
#pragma unroll
        for (int nt = 0; nt < 8; nt++)
#pragma unroll
            for (int j = 0; j < 4; j++) c[mt][nt][j] = 0.0f;

    constexpr int NCH = KT / KC;
    const int NPH = (DUAL ? 2 : 1) * NCH;

    for (int ph = 0; ph < NPH; ph++) {
        int srcidx = ph / NCH;
        int ch     = ph % NCH;
        const float* A = (DUAL && srcidx) ? A2 : A1;
        const float* B = (DUAL && srcidx) ? B2 : B1;
        if (ph) __syncthreads();

        // load 128x64 fp32 -> hi/lo bf16x2 smem tiles (8 float4 / thread)
#pragma unroll
        for (int q = 0; q < (128 * (KC / 4)) / NTHREADS; q++) {
            int id  = tid + NTHREADS * q;
            int row = id >> 4;            // 16 float4 per row
            int k   = (id & 15) * 4;
            int kw  = k >> 1;             // word index
            int grow = m0 + row;

            float4 va = make_float4(0.f, 0.f, 0.f, 0.f);
            if (grow < M)
                va = *reinterpret_cast<const float4*>(A + (size_t)grow * KT + ch * KC + k);
            uint32_t h0, l0, h1, l1;
            split_bf2(va.x, va.y, h0, l0);
            split_bf2(va.z, va.w, h1, l1);
            AsH[row * SW + kw]     = h0;
            AsH[row * SW + kw + 1] = h1;
            AsL[row * SW + kw]     = l0;
            AsL[row * SW + kw + 1] = l1;

            float4 vb = *reinterpret_cast<const float4*>(B + (size_t)row * KT + ch * KC + k);
            split_bf2(vb.x, vb.y, h0, l0);
            split_bf2(vb.z, vb.w, h1, l1);
            BsH[row * SW + kw]     = h0;
            BsH[row * SW + kw + 1] = h1;
            BsL[row * SW + kw]     = l0;
            BsL[row * SW + kw + 1] = l1;
        }
        __syncthreads();

#pragma unroll
        for (int kw0 = 0; kw0 < KC / 2; kw0 += 8) {     // k-step of 16
            uint32_t ah[2][4], al[2][4];
#pragma unroll
            for (int mt = 0; mt < 2; mt++) {
                int rlo = wm + mt * 16 + gr;
                ah[mt][0] = AsH[rlo * SW + kw0 + gc];
                ah[mt][1] = AsH[(rlo + 8) * SW + kw0 + gc];
                ah[mt][2] = AsH[rlo * SW + kw0 + gc + 4];
                ah[mt][3] = AsH[(rlo + 8) * SW + kw0 + gc + 4];
                al[mt][0] = AsL[rlo * SW + kw0 + gc];
                al[mt][1] = AsL[(rlo + 8) * SW + kw0 + gc];
                al[mt][2] = AsL[rlo * SW + kw0 + gc + 4];
                al[mt][3] = AsL[(rlo + 8) * SW + kw0 + gc + 4];
            }
#pragma unroll
            for (int nt = 0; nt < 8; nt++) {
                int col = wn + nt * 8 + gr;
                uint32_t bh[2], bl[2];
                bh[0] = BsH[col * SW + kw0 + gc];
                bh[1] = BsH[col * SW + kw0 + gc + 4];
                bl[0] = BsL[col * SW + kw0 + gc];
                bl[1] = BsL[col * SW + kw0 + gc + 4];
#pragma unroll
                for (int mt = 0; mt < 2; mt++) {
                    mma_bf16(c[mt][nt], ah[mt], bl);
                    mma_bf16(c[mt][nt], al[mt], bh);
                    mma_bf16(c[mt][nt], ah[mt], bh);
                }
            }
        }
    }

    // --- epilogue (c layout identical to m16n8k8) ---
    if (!HEAD) {
#pragma unroll
        for (int mt = 0; mt < 2; mt++) {
            int rlo = m0 + wm + mt * 16 + gr;
            int rhi = rlo + 8;
#pragma unroll
            for (int nt = 0; nt < 8; nt++) {
                int col = wn + nt * 8 + 2 * gc;
                float b0 = bias[col], b1 = bias[col + 1];
                if (rlo < M) {
                    float2 o;
                    o.x = fmaxf(c[mt][nt][0] + b0, 0.f);
                    o.y = fmaxf(c[mt][nt][1] + b1, 0.f);
                    *reinterpret_cast<float2*>(Y + (size_t)rlo * HID + col) = o;
                }
                if (rhi < M) {
                    float2 o;
                    o.x = fmaxf(c[mt][nt][2] + b0, 0.f);
                    o.y = fmaxf(c[mt][nt][3] + b1, 0.f);
                    *reinterpret_cast<float2*>(Y + (size_t)rhi * HID + col) = o;
                }
            }
        }
    } else {
#pragma unroll
        for (int mt = 0; mt < 2; mt++) {
            float plo = 0.f, phi = 0.f;
#pragma unroll
            for (int nt = 0; nt < 8; nt++) {
                int col = wn + nt * 8 + 2 * gc;
                float b0 = bias[col], b1 = bias[col + 1];
                float w0 = Wprd[col], w1 = Wprd[col + 1];
                plo += fmaxf(c[mt][nt][0] + b0, 0.f) * w0 +
                       fmaxf(c[mt][nt][1] + b1, 0.f) * w1;
                phi += fmaxf(c[mt][nt][2] + b0, 0.f) * w0 +
                       fmaxf(c[mt][nt][3] + b1, 0.f) * w1;
            }
            plo += __shfl_xor_sync(0xFFFFFFFFu, plo, 1);
            plo += __shfl_xor_sync(0xFFFFFFFFu, plo, 2);
            phi += __shfl_xor_sync(0xFFFFFFFFu, phi, 1);
            phi += __shfl_xor_sync(0xFFFFFFFFu, phi, 2);
            if (gc == 0) {
                red[wm + mt * 16 + gr][warp & 1]     = plo;
                red[wm + mt * 16 + gr + 8][warp & 1] = phi;
            }
        }
        __syncthreads();
        if (tid < 128) {
            int row = m0 + tid;
            if (row < M) Y[row] = red[tid][0] + red[tid][1] + bprd[0];
        }
    }
}

// ---------------------------------------------------------------------------
#define GEMM_SMEM (4 * 128 * SW * 4)

extern "C" void kernel_launch(void* const* d_in, const int* in_sizes, int n_in,
                              void* d_out, int out_size) {
    const float* x     = (const float*)d_in[0];   // (N,1,64)
    const int*   ei    = (const int*)d_in[1];     // (2,E) int32
    const float* ew    = (const float*)d_in[2];
    const float* Wrel0 = (const float*)d_in[3];
    const float* brel0 = (const float*)d_in[4];
    const float* Wroot0= (const float*)d_in[5];
    const float* Wro0  = (const float*)d_in[6];
    const float* bro0  = (const float*)d_in[7];
    const float* Wrel1 = (const float*)d_in[8];
    const float* brel1 = (const float*)d_in[9];
    const float* Wroot1= (const float*)d_in[10];
    const float* Wro1  = (const float*)d_in[11];
    const float* bro1  = (const float*)d_in[12];
    const float* Wprd  = (const float*)d_in[13];
    const float* bprd  = (const float*)d_in[14];
    float*       out   = (float*)d_out;

    int N = in_sizes[0] / IN_CH;  // 50000
    int E = in_sizes[2];          // 800000

    float* agg; cudaGetSymbolAddress((void**)&agg, g_agg);
    float* h1;  cudaGetSymbolAddress((void**)&h1,  g_h1);
    float* h2;  cudaGetSymbolAddress((void**)&h2,  g_h2);

    cudaFuncSetAttribute(mma_gemm<IN_CH, true,  false>, cudaFuncAttributeMaxDynamicSharedMemorySize, GEMM_SMEM);
    cudaFuncSetAttribute(mma_gemm<HID,   false, false>, cudaFuncAttributeMaxDynamicSharedMemorySize, GEMM_SMEM);
    cudaFuncSetAttribute(mma_gemm<HID,   true,  false>, cudaFuncAttributeMaxDynamicSharedMemorySize, GEMM_SMEM);
    cudaFuncSetAttribute(mma_gemm<HID,   false, true >, cudaFuncAttributeMaxDynamicSharedMemorySize, GEMM_SMEM);

    int gb = (N + 127) / 128;

    // --- CSR build (shared by both layers) ---
    zero_deg<<<(N + 255) / 256, 256>>>(N);
    hist<<<(E + 255) / 256, 256>>>(ei, E);
    scan_all<<<1, 1024>>>(N);
    fill<<<(E + 255) / 256, 256>>>(ei, ew, E);

    // --- layer 0 ---
    gather64<<<(N * 32 + 255) / 256, 256>>>(x, N);
    mma_gemm<IN_CH, true, false><<<gb, NTHREADS, GEMM_SMEM>>>(
        agg, Wrel0, x, Wroot0, brel0, nullptr, nullptr, h1, N);
    mma_gemm<HID, false, false><<<gb, NTHREADS, GEMM_SMEM>>>(
        h1, Wro0, nullptr, nullptr, bro0, nullptr, nullptr, h2, N);

    // --- layer 1 ---
    gather128<<<(N * 32 + 255) / 256, 256>>>(h2, N);
    mma_gemm<HID, true, false><<<gb, NTHREADS, GEMM_SMEM>>>(
        agg, Wrel1, h2, Wroot1, brel1, nullptr, nullptr, h1, N);

    // ro1 + head fused
    mma_gemm<HID, false, true><<<gb, NTHREADS, GEMM_SMEM>>>(
        h1, Wro1, nullptr, nullptr, bro1, Wprd, bprd, out, N);
}